// round 10
// baseline (speedup 1.0000x reference)
#include <cuda_runtime.h>

namespace {
constexpr int W = 512, H = 512, OW = 506, OH = 506, CH = 96;
constexpr int NB = 20;                 // bands per channel
constexpr int BH = 26;                 // output rows per band (last: 12)
constexpr int NWARPS = CH * NB;        // 1920 independent warps

constexpr float C1f = 0.01f * 0.01f;
constexpr float C2f = 0.03f * 0.03f;
constexpr float INV  = 1.0f / 49.0f;
constexpr float INV2 = INV * INV;
constexpr float COV  = 49.0f / 48.0f;
constexpr float kA  = 2.0f * INV2;
constexpr float kC  = INV2;
constexpr float kB1 = 2.0f * COV * INV;
constexpr float kB2 = 2.0f * COV * INV2;
constexpr float kD1 = COV * INV;       // D = kD1*Szz - kD2*Q + C2, Szz = Sxx+Syy
constexpr float kD2 = COV * INV2;
}

__device__ double g_partials[NWARPS];
__device__ unsigned int g_count = 0;

__global__ __launch_bounds__(32) void ssim_warp(const float* __restrict__ X,
                                                const float* __restrict__ Y,
                                                float* __restrict__ out) {
    const int wid = blockIdx.x;
    const int ch = wid / NB;
    const int band = wid - ch * NB;
    const int lane = threadIdx.x;
    const float* __restrict__ x = X + (size_t)ch * H * W;
    const float* __restrict__ y = Y + (size_t)ch * H * W;
    const int r0 = band * BH;
    const int rEnd = min(r0 + BH, OH);
    const int colbase = 4 * lane;      // group g at cols 128g + 4*lane (coalesced)

    // 4 quantities (Sx, Sy, Szz=Sxx+Syy, Sxy) x 16 cols
    float s[4][16];
#pragma unroll
    for (int q = 0; q < 4; q++)
#pragma unroll
        for (int i = 0; i < 16; i++) s[q][i] = 0.0f;

    // prologue: accumulate 7 input rows
#pragma unroll
    for (int rr = 0; rr < 7; rr++) {
        const size_t rowoff = (size_t)(r0 + rr) * W + colbase;
#pragma unroll
        for (int g = 0; g < 4; g++) {
            const float4 xv = *(const float4*)(x + rowoff + 128 * g);
            const float4 yv = *(const float4*)(y + rowoff + 128 * g);
            const float xa[4] = {xv.x, xv.y, xv.z, xv.w};
            const float ya[4] = {yv.x, yv.y, yv.z, yv.w};
#pragma unroll
            for (int j = 0; j < 4; j++) {
                const int i = 4 * g + j;
                s[0][i] += xa[j];
                s[1][i] += ya[j];
                s[2][i] = fmaf(xa[j], xa[j], fmaf(ya[j], ya[j], s[2][i]));
                s[3][i] = fmaf(xa[j], ya[j], s[3][i]);
            }
        }
    }

    float acc = 0.0f;

    // prefetch buffer: next iteration's new row (r+6) and old row (r-1)
    float4 pxn[4], pyn[4], pxo[4], pyo[4];

#define LOADP(rr)                                                             \
    {                                                                         \
        const size_t rn_ = (size_t)((rr) + 6) * W + colbase;                  \
        const size_t ro_ = (size_t)((rr) - 1) * W + colbase;                  \
        _Pragma("unroll")                                                     \
        for (int g = 0; g < 4; g++) {                                         \
            pxn[g] = *(const float4*)(x + rn_ + 128 * g);                     \
            pyn[g] = *(const float4*)(y + rn_ + 128 * g);                     \
            pxo[g] = *(const float4*)(x + ro_ + 128 * g);                     \
            pyo[g] = *(const float4*)(y + ro_ + 128 * g);                     \
        }                                                                     \
    }

#define CONSUME()                                                             \
    {                                                                         \
        _Pragma("unroll")                                                     \
        for (int g = 0; g < 4; g++) {                                         \
            const float xn[4] = {pxn[g].x, pxn[g].y, pxn[g].z, pxn[g].w};     \
            const float yn[4] = {pyn[g].x, pyn[g].y, pyn[g].z, pyn[g].w};     \
            const float xo[4] = {pxo[g].x, pxo[g].y, pxo[g].z, pxo[g].w};     \
            const float yo[4] = {pyo[g].x, pyo[g].y, pyo[g].z, pyo[g].w};     \
            _Pragma("unroll")                                                 \
            for (int j = 0; j < 4; j++) {                                     \
                const int i = 4 * g + j;                                      \
                s[0][i] += xn[j] - xo[j];                                     \
                s[1][i] += yn[j] - yo[j];                                     \
                s[2][i] = fmaf(xn[j], xn[j],                                  \
                          fmaf(yn[j], yn[j],                                  \
                          fmaf(-xo[j], xo[j],                                 \
                          fmaf(-yo[j], yo[j], s[2][i]))));                    \
                s[3][i] = fmaf(xn[j], yn[j], fmaf(-xo[j], yo[j], s[3][i]));   \
            }                                                                 \
        }                                                                     \
    }

    // process_row: horizontal 7-windows via shuffles + SSIM for 16 outputs
#define PROCESS_ROW()                                                         \
    {                                                                         \
        float cS0[4], cP01[4], cP012[4], cS4[4];                              \
        _Pragma("unroll")                                                     \
        for (int q = 0; q < 4; q++) {                                         \
            cS0[q] = s[q][0];                                                 \
            cP01[q] = s[q][0] + s[q][1];                                      \
            cP012[q] = cP01[q] + s[q][2];                                     \
            cS4[q] = cP012[q] + s[q][3];                                      \
        }                                                                     \
        _Pragma("unroll")                                                     \
        for (int g = 0; g < 4; g++) {                                         \
            float nS0[4], nP01[4], nP012[4], nS4[4];                          \
            if (g < 3) {                                                      \
                _Pragma("unroll")                                             \
                for (int q = 0; q < 4; q++) {                                 \
                    nS0[q] = s[q][4 * g + 4];                                 \
                    nP01[q] = nS0[q] + s[q][4 * g + 5];                       \
                    nP012[q] = nP01[q] + s[q][4 * g + 6];                     \
                    nS4[q] = nP012[q] + s[q][4 * g + 7];                      \
                }                                                             \
            } else {                                                          \
                _Pragma("unroll")                                             \
                for (int q = 0; q < 4; q++) {                                 \
                    nS0[q] = cS0[q]; nP01[q] = cP01[q];                       \
                    nP012[q] = cP012[q]; nS4[q] = cS4[q];                     \
                }                                                             \
            }                                                                 \
            float w[4][4];                                                    \
            _Pragma("unroll")                                                 \
            for (int q = 0; q < 4; q++) {                                     \
                const bool b1 = (g < 3) && (lane == 0);                       \
                const bool b2 = (g < 3) && (lane < 2);                        \
                const float pA1 = b1 ? nP012[q] : cP012[q];                   \
                const float pA2 = b1 ? nS4[q]   : cS4[q];                     \
                const float pB1 = b2 ? nS0[q]   : cS0[q];                     \
                const float pB2 = b2 ? nP01[q]  : cP01[q];                    \
                const float A1 = __shfl_sync(0xffffffffu, pA1, (lane + 1) & 31); \
                const float A2 = __shfl_sync(0xffffffffu, pA2, (lane + 1) & 31); \
                const float B1 = __shfl_sync(0xffffffffu, pB1, (lane + 2) & 31); \
                const float B2 = __shfl_sync(0xffffffffu, pB2, (lane + 2) & 31); \
                w[q][0] = cS4[q] + A1;                                        \
                w[q][1] = (cS4[q] - cS0[q]) + A2;                             \
                w[q][2] = (cS4[q] - cP01[q]) + A2 + B1;                       \
                w[q][3] = (cS4[q] - cP012[q]) + A2 + B2;                      \
            }                                                                 \
            float num[4], den[4];                                             \
            _Pragma("unroll")                                                 \
            for (int k = 0; k < 4; k++) {                                     \
                const float Sx = w[0][k], Sy = w[1][k];                       \
                const float Szz = w[2][k], Sxy = w[3][k];                     \
                const float Pm = Sx * Sy;                                     \
                const float Q = fmaf(Sx, Sx, Sy * Sy);                        \
                const float A = fmaf(kA, Pm, C1f);                            \
                const float Cc = fmaf(kC, Q, C1f);                            \
                const float B = fmaf(kB1, Sxy, fmaf(-kB2, Pm, C2f));          \
                const float D = fmaf(kD1, Szz, fmaf(-kD2, Q, C2f));           \
                num[k] = A * B;                                               \
                den[k] = Cc * D;                                              \
            }                                                                 \
            if (g == 3) {                                                     \
                /* only cols >= 506 invalid: group 3, lanes 30/31 */          \
                const int c0 = 384 + colbase;                                 \
                _Pragma("unroll")                                             \
                for (int k = 0; k < 4; k++) {                                 \
                    const bool valid = (c0 + k) < OW;                         \
                    num[k] = valid ? num[k] : 0.0f;                           \
                    den[k] = valid ? den[k] : 1.0f;                           \
                }                                                             \
            }                                                                 \
            const float p01 = den[0] * den[1];                                \
            const float p012 = p01 * den[2];                                  \
            const float rall = 1.0f / (p012 * den[3]);                        \
            const float r3 = rall * p012;                                     \
            const float r012 = rall * den[3];                                 \
            const float r2 = r012 * p01;                                      \
            const float r01 = r012 * den[2];                                  \
            acc = fmaf(num[0], r01 * den[1],                                  \
                  fmaf(num[1], r01 * den[0],                                  \
                  fmaf(num[2], r2,                                            \
                  fmaf(num[3], r3, acc))));                                   \
            if (g < 3) {                                                      \
                _Pragma("unroll")                                             \
                for (int q = 0; q < 4; q++) {                                 \
                    cS0[q] = nS0[q]; cP01[q] = nP01[q];                       \
                    cP012[q] = nP012[q]; cS4[q] = nS4[q];                     \
                }                                                             \
            }                                                                 \
        }                                                                     \
    }

    // software-pipelined main loop: loads for iter r+1 issue before iter r's math
    LOADP(r0 + 1);
    PROCESS_ROW();     // row r0 (sums valid from prologue)

    for (int r = r0 + 1; r < rEnd; r++) {
        CONSUME();                       // fold prefetched rows into sums
        if (r + 1 < rEnd) LOADP(r + 1);  // issue next loads early (hide latency)
        PROCESS_ROW();                   // math overlaps in-flight loads
    }

#undef LOADP
#undef CONSUME
#undef PROCESS_ROW

    // warp tree-reduce (fixed order -> deterministic)
#pragma unroll
    for (int off = 16; off > 0; off >>= 1)
        acc += __shfl_down_sync(0xffffffffu, acc, off);

    int last = 0;
    if (lane == 0) {
        g_partials[wid] = (double)acc;
        __threadfence();
        const unsigned int c = atomicInc(&g_count, NWARPS - 1);  // wraps to 0
        last = (c == NWARPS - 1) ? 1 : 0;
    }
    last = __shfl_sync(0xffffffffu, last, 0);

    if (last) {
        const volatile double* vp = g_partials;
        double sd = 0.0;
        for (int i = lane; i < NWARPS; i += 32) sd += vp[i];
#pragma unroll
        for (int off = 16; off > 0; off >>= 1)
            sd += __shfl_down_sync(0xffffffffu, sd, off);
        if (lane == 0)
            out[0] = (float)(sd / ((double)CH * (double)OH * (double)OW));
    }
}

extern "C" void kernel_launch(void* const* d_in, const int* in_sizes, int n_in,
                              void* d_out, int out_size) {
    const float* x = (const float*)d_in[0];
    const float* y = (const float*)d_in[1];
    float* out = (float*)d_out;
    ssim_warp<<<NWARPS, 32>>>(x, y, out);
}

// round 11
// speedup vs baseline: 1.2924x; 1.2924x over previous
#include <cuda_runtime.h>

namespace {
constexpr int W = 512, H = 512, OW = 506, OH = 506, CH = 96;
constexpr int NB = 16;                 // bands per channel
constexpr int BH = 32;                 // output rows per band (last: 26)
constexpr int NWARPS = CH * NB;        // 1536 independent warps

constexpr float C1f = 0.01f * 0.01f;
constexpr float C2f = 0.03f * 0.03f;
constexpr float INV  = 1.0f / 49.0f;
constexpr float INV2 = INV * INV;
constexpr float COV  = 49.0f / 48.0f;
constexpr float kA  = 2.0f * INV2;
constexpr float kC  = INV2;
constexpr float kB1 = 2.0f * COV * INV;
constexpr float kB2 = 2.0f * COV * INV2;
constexpr float kD1 = COV * INV;       // D = kD1*Szz - kD2*Q + C2, Szz = Sxx+Syy
constexpr float kD2 = COV * INV2;
}

__device__ double g_partials[NWARPS];
__device__ unsigned int g_count = 0;

__global__ __launch_bounds__(32) void ssim_warp(const float* __restrict__ X,
                                                const float* __restrict__ Y,
                                                float* __restrict__ out) {
    const int wid = blockIdx.x;
    const int ch = wid >> 4;
    const int band = wid & (NB - 1);
    const int lane = threadIdx.x;
    const float* __restrict__ x = X + (size_t)ch * H * W;
    const float* __restrict__ y = Y + (size_t)ch * H * W;
    const int r0 = band * BH;
    const int rEnd = min(r0 + BH, OH);
    const int colbase = 4 * lane;      // group g at cols 128g + 4*lane (coalesced)

    // 4 quantities (Sx, Sy, Szz=Sxx+Syy, Sxy) x 16 cols
    float s[4][16];
#pragma unroll
    for (int q = 0; q < 4; q++)
#pragma unroll
        for (int i = 0; i < 16; i++) s[q][i] = 0.0f;

    // prologue: accumulate 7 input rows
#pragma unroll
    for (int rr = 0; rr < 7; rr++) {
        const size_t rowoff = (size_t)(r0 + rr) * W + colbase;
#pragma unroll
        for (int g = 0; g < 4; g++) {
            const float4 xv = *(const float4*)(x + rowoff + 128 * g);
            const float4 yv = *(const float4*)(y + rowoff + 128 * g);
            const float xa[4] = {xv.x, xv.y, xv.z, xv.w};
            const float ya[4] = {yv.x, yv.y, yv.z, yv.w};
#pragma unroll
            for (int j = 0; j < 4; j++) {
                const int i = 4 * g + j;
                s[0][i] += xa[j];
                s[1][i] += ya[j];
                s[2][i] = fmaf(xa[j], xa[j], fmaf(ya[j], ya[j], s[2][i]));
                s[3][i] = fmaf(xa[j], ya[j], s[3][i]);
            }
        }
    }

    float accA = 0.0f, accB = 0.0f;   // independent chains (groups 0,1 / 2,3)

    // prefetch buffer: next iteration's new row (r+6) and old row (r-1)
    float4 pxn[4], pyn[4], pxo[4], pyo[4];

#define LOADP(rr)                                                             \
    {                                                                         \
        const size_t rn_ = (size_t)((rr) + 6) * W + colbase;                  \
        const size_t ro_ = (size_t)((rr) - 1) * W + colbase;                  \
        _Pragma("unroll")                                                     \
        for (int g = 0; g < 4; g++) {                                         \
            pxn[g] = *(const float4*)(x + rn_ + 128 * g);                     \
            pyn[g] = *(const float4*)(y + rn_ + 128 * g);                     \
            pxo[g] = *(const float4*)(x + ro_ + 128 * g);                     \
            pyo[g] = *(const float4*)(y + ro_ + 128 * g);                     \
        }                                                                     \
    }

#define CONSUME()                                                             \
    {                                                                         \
        _Pragma("unroll")                                                     \
        for (int g = 0; g < 4; g++) {                                         \
            const float xn[4] = {pxn[g].x, pxn[g].y, pxn[g].z, pxn[g].w};     \
            const float yn[4] = {pyn[g].x, pyn[g].y, pyn[g].z, pyn[g].w};     \
            const float xo[4] = {pxo[g].x, pxo[g].y, pxo[g].z, pxo[g].w};     \
            const float yo[4] = {pyo[g].x, pyo[g].y, pyo[g].z, pyo[g].w};     \
            _Pragma("unroll")                                                 \
            for (int j = 0; j < 4; j++) {                                     \
                const int i = 4 * g + j;                                      \
                s[0][i] += xn[j] - xo[j];                                     \
                s[1][i] += yn[j] - yo[j];                                     \
                s[2][i] = fmaf(xn[j], xn[j],                                  \
                          fmaf(yn[j], yn[j],                                  \
                          fmaf(-xo[j], xo[j],                                 \
                          fmaf(-yo[j], yo[j], s[2][i]))));                    \
                s[3][i] = fmaf(xn[j], yn[j], fmaf(-xo[j], yo[j], s[3][i]));   \
            }                                                                 \
        }                                                                     \
    }

    // process_row: horizontal 7-windows via shuffles + SSIM for 16 outputs
#define PROCESS_ROW()                                                         \
    {                                                                         \
        float cS0[4], cP01[4], cP012[4], cS4[4];                              \
        _Pragma("unroll")                                                     \
        for (int q = 0; q < 4; q++) {                                         \
            cS0[q] = s[q][0];                                                 \
            cP01[q] = s[q][0] + s[q][1];                                      \
            cP012[q] = cP01[q] + s[q][2];                                     \
            cS4[q] = cP012[q] + s[q][3];                                      \
        }                                                                     \
        _Pragma("unroll")                                                     \
        for (int g = 0; g < 4; g++) {                                         \
            float nS0[4], nP01[4], nP012[4], nS4[4];                          \
            if (g < 3) {                                                      \
                _Pragma("unroll")                                             \
                for (int q = 0; q < 4; q++) {                                 \
                    nS0[q] = s[q][4 * g + 4];                                 \
                    nP01[q] = nS0[q] + s[q][4 * g + 5];                       \
                    nP012[q] = nP01[q] + s[q][4 * g + 6];                     \
                    nS4[q] = nP012[q] + s[q][4 * g + 7];                      \
                }                                                             \
            } else {                                                          \
                _Pragma("unroll")                                             \
                for (int q = 0; q < 4; q++) {                                 \
                    nS0[q] = cS0[q]; nP01[q] = cP01[q];                       \
                    nP012[q] = cP012[q]; nS4[q] = cS4[q];                     \
                }                                                             \
            }                                                                 \
            float w[4][4];                                                    \
            _Pragma("unroll")                                                 \
            for (int q = 0; q < 4; q++) {                                     \
                const bool b1 = (g < 3) && (lane == 0);                       \
                const bool b2 = (g < 3) && (lane < 2);                        \
                const float pA1 = b1 ? nP012[q] : cP012[q];                   \
                const float pA2 = b1 ? nS4[q]   : cS4[q];                     \
                const float pB1 = b2 ? nS0[q]   : cS0[q];                     \
                const float pB2 = b2 ? nP01[q]  : cP01[q];                    \
                const float A1 = __shfl_sync(0xffffffffu, pA1, (lane + 1) & 31); \
                const float A2 = __shfl_sync(0xffffffffu, pA2, (lane + 1) & 31); \
                const float B1 = __shfl_sync(0xffffffffu, pB1, (lane + 2) & 31); \
                const float B2 = __shfl_sync(0xffffffffu, pB2, (lane + 2) & 31); \
                w[q][0] = cS4[q] + A1;                                        \
                w[q][1] = (cS4[q] - cS0[q]) + A2;                             \
                w[q][2] = (cS4[q] - cP01[q]) + A2 + B1;                       \
                w[q][3] = (cS4[q] - cP012[q]) + A2 + B2;                      \
            }                                                                 \
            float num[4], den[4];                                             \
            _Pragma("unroll")                                                 \
            for (int k = 0; k < 4; k++) {                                     \
                const float Sx = w[0][k], Sy = w[1][k];                       \
                const float Szz = w[2][k], Sxy = w[3][k];                     \
                const float Pm = Sx * Sy;                                     \
                const float Q = fmaf(Sx, Sx, Sy * Sy);                        \
                const float A = fmaf(kA, Pm, C1f);                            \
                const float Cc = fmaf(kC, Q, C1f);                            \
                const float B = fmaf(kB1, Sxy, fmaf(-kB2, Pm, C2f));          \
                const float D = fmaf(kD1, Szz, fmaf(-kD2, Q, C2f));           \
                num[k] = A * B;                                               \
                den[k] = Cc * D;                                              \
            }                                                                 \
            if (g == 3) {                                                     \
                /* only cols >= 506 invalid: group 3, lanes 30/31 */          \
                const int c0 = 384 + colbase;                                 \
                _Pragma("unroll")                                             \
                for (int k = 0; k < 4; k++) {                                 \
                    const bool valid = (c0 + k) < OW;                         \
                    num[k] = valid ? num[k] : 0.0f;                           \
                    den[k] = valid ? den[k] : 1.0f;                           \
                }                                                             \
            }                                                                 \
            const float p01 = den[0] * den[1];                                \
            const float p012 = p01 * den[2];                                  \
            const float rall = 1.0f / (p012 * den[3]);                        \
            const float r3 = rall * p012;                                     \
            const float r012 = rall * den[3];                                 \
            const float r2 = r012 * p01;                                      \
            const float r01 = r012 * den[2];                                  \
            const float contrib =                                             \
                fmaf(num[0], r01 * den[1],                                    \
                fmaf(num[1], r01 * den[0],                                    \
                fmaf(num[2], r2, num[3] * r3)));                              \
            if (g < 2) accA += contrib; else accB += contrib;                 \
            if (g < 3) {                                                      \
                _Pragma("unroll")                                             \
                for (int q = 0; q < 4; q++) {                                 \
                    cS0[q] = nS0[q]; cP01[q] = nP01[q];                       \
                    cP012[q] = nP012[q]; cS4[q] = nS4[q];                     \
                }                                                             \
            }                                                                 \
        }                                                                     \
    }

    // software-pipelined main loop: loads for iter r+1 issue before iter r's math
    LOADP(r0 + 1);
    PROCESS_ROW();     // row r0 (sums valid from prologue)

    for (int r = r0 + 1; r < rEnd; r++) {
        CONSUME();                       // fold prefetched rows into sums
        if (r + 1 < rEnd) LOADP(r + 1);  // issue next loads early (hide latency)
        PROCESS_ROW();                   // math overlaps in-flight loads
    }

#undef LOADP
#undef CONSUME
#undef PROCESS_ROW

    float acc = accA + accB;

    // warp tree-reduce (fixed order -> deterministic)
#pragma unroll
    for (int off = 16; off > 0; off >>= 1)
        acc += __shfl_down_sync(0xffffffffu, acc, off);

    int last = 0;
    if (lane == 0) {
        g_partials[wid] = (double)acc;
        __threadfence();
        const unsigned int c = atomicInc(&g_count, NWARPS - 1);  // wraps to 0
        last = (c == NWARPS - 1) ? 1 : 0;
    }
    last = __shfl_sync(0xffffffffu, last, 0);

    if (last) {
        const volatile double* vp = g_partials;
        double sd = 0.0;
        for (int i = lane; i < NWARPS; i += 32) sd += vp[i];
#pragma unroll
        for (int off = 16; off > 0; off >>= 1)
            sd += __shfl_down_sync(0xffffffffu, sd, off);
        if (lane == 0)
            out[0] = (float)(sd / ((double)CH * (double)OH * (double)OW));
    }
}

extern "C" void kernel_launch(void* const* d_in, const int* in_sizes, int n_in,
                              void* d_out, int out_size) {
    const float* x = (const float*)d_in[0];
    const float* y = (const float*)d_in[1];
    float* out = (float*)d_out;
    ssim_warp<<<NWARPS, 32>>>(x, y, out);
}